// round 5
// baseline (speedup 1.0000x reference)
#include <cuda_runtime.h>
#include <cstdint>

#define UNUM 100000
#define INUM 200000
#define NTOT 300000
#define NNZE 4000000
#define BSZ  4096
#define DIM  64
#define NLAY 3
#define CDIM2 192             // concat store: layers 1..3 only (layer0 read from inputs)
#define EMAX 96               // padded ELL row capacity (mean deg ~12)
#define RPB  256              // rows per combine block

// ---------------- scratch (static device globals; no allocs allowed) ----------------
__device__ __align__(256) float g_ego [(size_t)NTOT * DIM];          // 76.8 MB
__device__ __align__(256) float g_side[(size_t)NTOT * DIM];          // 76.8 MB
__device__ __align__(256) float g_all [(size_t)NTOT * CDIM2];        // 230 MB
__device__ __align__(256) int2  g_ell [(size_t)NTOT * EMAX];         // 230 MB {col, val bits}
__device__ __align__(256) int   g_cnt [NTOT];
__device__ float g_acc[2];                                           // bpr_sum, reg_sum

// ---------------- threefry2x32 (exact JAX semantics) ----------------
__host__ __device__ __forceinline__ uint32_t rotl32(uint32_t x, int r) {
    return (x << r) | (x >> (32 - r));
}

__host__ __device__ inline void threefry2x32(uint32_t k0, uint32_t k1,
                                             uint32_t x0, uint32_t x1,
                                             uint32_t &o0, uint32_t &o1) {
    uint32_t k2 = k0 ^ k1 ^ 0x1BD11BDAu;
    x0 += k0; x1 += k1;
#define TF_R(r) { x0 += x1; x1 = rotl32(x1, r); x1 ^= x0; }
    TF_R(13) TF_R(15) TF_R(26) TF_R(6)   x0 += k1; x1 += k2 + 1u;
    TF_R(17) TF_R(29) TF_R(16) TF_R(24)  x0 += k2; x1 += k0 + 2u;
    TF_R(13) TF_R(15) TF_R(26) TF_R(6)   x0 += k0; x1 += k1 + 3u;
    TF_R(17) TF_R(29) TF_R(16) TF_R(24)  x0 += k1; x1 += k2 + 4u;
    TF_R(13) TF_R(15) TF_R(26) TF_R(6)   x0 += k2; x1 += k0 + 5u;
#undef TF_R
    o0 = x0; o1 = x1;
}

// Partitionable (counter-mode) bits: threefry(key, (0, i)), 32-bit finisher o0^o1
__device__ __forceinline__ uint32_t rbits_partitionable(uint32_t k0, uint32_t k1, uint32_t i) {
    uint32_t o0, o1;
    threefry2x32(k0, k1, 0u, i, o0, o1);
    return o0 ^ o1;
}

__device__ __forceinline__ float u01(uint32_t bits) {
    return __uint_as_float((bits >> 9) | 0x3F800000u) - 1.0f;
}

// layer-aware ego row pointer (layer 0 reads raw inputs; layers >0 read g_ego)
__device__ __forceinline__ const float* ego_row(const float* eu, const float* ei, int r) {
    return (r < UNUM) ? eu + (size_t)r * DIM : ei + (size_t)(r - UNUM) * DIM;
}

// ---------------- kernels ----------------
// One pass: edge dropout + ELL scatter (dropped edges never stored). Also zeroes acc.
__global__ void scatter_kernel(const float* __restrict__ val, const int* __restrict__ row,
                               const int* __restrict__ col, uint32_t k0, uint32_t k1) {
    int e = blockIdx.x * blockDim.x + threadIdx.x;
    if (e == 0) { g_acc[0] = 0.f; g_acc[1] = 0.f; }
    if (e >= NNZE) return;
    float u = u01(rbits_partitionable(k0, k1, (uint32_t)e));
    if (u >= 0.9f) return;                 // dropped: contributes +0 exactly
    float v = val[e] * (1.0f / 0.9f);
    int r = row[e];
    int pos = atomicAdd(&g_cnt[r], 1);
    if (pos < EMAX)
        g_ell[(size_t)r * EMAX + pos] = make_int2(col[e], __float_as_int(v));
}

// Atomic-free SpMM: one warp per row; 2 edge-slots x 16 dim-lanes.
__global__ void spmm_kernel(const float* __restrict__ eu, const float* __restrict__ ei) {
    int w    = (blockIdx.x * blockDim.x + threadIdx.x) >> 5;
    if (w >= NTOT) return;
    int lane = threadIdx.x & 31;
    int sub  = lane >> 4;       // which edge slot
    int dl   = lane & 15;       // dim quarter (float4)
    int cnt  = g_cnt[w];
    if (cnt > EMAX) cnt = EMAX;
    const int2* ep = g_ell + (size_t)w * EMAX;
    float4 acc = make_float4(0.f, 0.f, 0.f, 0.f);
    for (int j = sub; j < cnt; j += 2) {
        int2 cv = ep[j];
        float v = __int_as_float(cv.y);
        float4 x = ((const float4*)ego_row(eu, ei, cv.x))[dl];
        acc.x += v * x.x; acc.y += v * x.y; acc.z += v * x.z; acc.w += v * x.w;
    }
    acc.x += __shfl_xor_sync(0xFFFFFFFFu, acc.x, 16);
    acc.y += __shfl_xor_sync(0xFFFFFFFFu, acc.y, 16);
    acc.z += __shfl_xor_sync(0xFFFFFFFFu, acc.z, 16);
    acc.w += __shfl_xor_sync(0xFFFFFFFFu, acc.w, 16);
    if (sub == 0)
        ((float4*)(g_side + (size_t)w * DIM))[dl] = acc;
}

// Fused: side@Wg + b + (ego*side)@Wb + b -> leaky_relu -> msg dropout -> L2 norm.
// Dropped un-normalized -> g_ego (unless last layer); normalized -> g_all block.
// 256 threads, 256 rows/block, 4 rows x 16 cols per thread.
__global__ void __launch_bounds__(256, 1)
combine_kernel(const float* __restrict__ Wg, const float* __restrict__ bg,
               const float* __restrict__ Wb, const float* __restrict__ bb,
               const float* __restrict__ eu, const float* __restrict__ ei,
               uint32_t mk0, uint32_t mk1, int layer, int write_ego) {
    extern __shared__ float sm[];
    float*  sWg = sm;                       // 4096
    float*  sWb = sm + 4096;                // 4096
    float2* sSE = (float2*)(sm + 8192);     // 4 planes x 64 x 65 float2 {s, e*s}
    const int PL2 = 64 * 65;
    float*  ssum = sm + 8192 + 4 * PL2 * 2; // 256 x 4
    int tid  = threadIdx.x;
    int row0 = blockIdx.x * RPB;

    for (int i = tid; i < 4096; i += 256) { sWg[i] = Wg[i]; sWb[i] = Wb[i]; }
    for (int i = tid; i < RPB * 16; i += 256) {
        int r = i >> 4, q = i & 15;
        int gr = row0 + r;
        float4 s = make_float4(0.f, 0.f, 0.f, 0.f), e = s;
        if (gr < NTOT) {
            s = ((const float4*)(g_side + (size_t)gr * DIM))[q];
            e = ((const float4*)ego_row(eu, ei, gr))[q];
        }
        int p = r & 3, rp = r >> 2;
        float2* d = &sSE[p * PL2 + rp * 65 + q * 4];
        d[0] = make_float2(s.x, s.x * e.x);
        d[1] = make_float2(s.y, s.y * e.y);
        d[2] = make_float2(s.z, s.z * e.z);
        d[3] = make_float2(s.w, s.w * e.w);
    }
    __syncthreads();

    int cg = tid >> 6;           // 0..3 column group (warp-uniform)
    int rp = tid & 63;           // row group (handles rows 4*rp .. 4*rp+3)
    int c0 = cg * 16;
    float acc[4][16];
#pragma unroll
    for (int c = 0; c < 16; c++) {
        float b = bg[c0 + c] + bb[c0 + c];
#pragma unroll
        for (int p = 0; p < 4; p++) acc[p][c] = b;
    }

    for (int j = 0; j < 64; j++) {
        float2 se0 = sSE[0 * PL2 + rp * 65 + j];
        float2 se1 = sSE[1 * PL2 + rp * 65 + j];
        float2 se2 = sSE[2 * PL2 + rp * 65 + j];
        float2 se3 = sSE[3 * PL2 + rp * 65 + j];
        const float4* wg4 = (const float4*)&sWg[j * 64 + c0];
        const float4* wb4 = (const float4*)&sWb[j * 64 + c0];
#pragma unroll
        for (int q = 0; q < 4; q++) {
            float4 wg = wg4[q], wb = wb4[q];
#define ACC1(P, SE) \
            acc[P][4*q+0] += SE.x * wg.x + SE.y * wb.x; \
            acc[P][4*q+1] += SE.x * wg.y + SE.y * wb.y; \
            acc[P][4*q+2] += SE.x * wg.z + SE.y * wb.z; \
            acc[P][4*q+3] += SE.x * wg.w + SE.y * wb.w;
            ACC1(0, se0) ACC1(1, se1) ACC1(2, se2) ACC1(3, se3)
#undef ACC1
        }
    }

    // epilogue: leaky-relu + message dropout + partial row sums
#pragma unroll
    for (int p = 0; p < 4; p++) {
        int gr = row0 + rp * 4 + p;
        float ss = 0.f;
        if (gr < NTOT) {
            uint32_t ib = (uint32_t)gr * 64u + (uint32_t)c0;
#pragma unroll
            for (int c = 0; c < 16; c++) {
                float a = acc[p][c];
                a = (a >= 0.f) ? a : 0.2f * a;
                float u = u01(rbits_partitionable(mk0, mk1, ib + (uint32_t)c));
                a = (u < 0.9f) ? a * (1.0f / 0.9f) : 0.f;
                acc[p][c] = a;
                ss += a * a;
            }
        }
        ssum[(rp * 4 + p) * 4 + cg] = ss;
    }
    __syncthreads();

#pragma unroll
    for (int p = 0; p < 4; p++) {
        int gr = row0 + rp * 4 + p;
        if (gr >= NTOT) continue;
        int rb = rp * 4 + p;
        float tot = ssum[rb * 4 + 0] + ssum[rb * 4 + 1] + ssum[rb * 4 + 2] + ssum[rb * 4 + 3];
        float inv = 1.0f / fmaxf(sqrtf(tot), 1e-12f);
        float4* dn = (float4*)(g_all + (size_t)gr * CDIM2 + (size_t)layer * DIM + c0);
#pragma unroll
        for (int q = 0; q < 4; q++)
            dn[q] = make_float4(acc[p][4*q+0] * inv, acc[p][4*q+1] * inv,
                                acc[p][4*q+2] * inv, acc[p][4*q+3] * inv);
        if (write_ego) {
            float4* de = (float4*)(g_ego + (size_t)gr * DIM + c0);
#pragma unroll
            for (int q = 0; q < 4; q++)
                de[q] = make_float4(acc[p][4*q+0], acc[p][4*q+1],
                                    acc[p][4*q+2], acc[p][4*q+3]);
        }
    }
}

// warp per sample: BPR + reg partial sums. Concat = [raw emb | g_all(192)].
__global__ void loss_kernel(const float* __restrict__ ue0, const float* __restrict__ ie0,
                            const int* __restrict__ uid, const int* __restrict__ pid,
                            const int* __restrict__ nid) {
    int w    = (blockIdx.x * blockDim.x + threadIdx.x) >> 5;
    int lane = threadIdx.x & 31;
    if (w >= BSZ) return;
    int u = uid[w], p = pid[w], n = nid[w];
    // lane covers 8 consecutive concat cols at lane*8; cols<64 from raw emb
    const float* au = (lane < 8) ? ue0 + (size_t)u * DIM + lane * 8
                                 : g_all + (size_t)u * CDIM2 + lane * 8 - 64;
    const float* bp = (lane < 8) ? ie0 + (size_t)p * DIM + lane * 8
                                 : g_all + (size_t)(UNUM + p) * CDIM2 + lane * 8 - 64;
    const float* bn = (lane < 8) ? ie0 + (size_t)n * DIM + lane * 8
                                 : g_all + (size_t)(UNUM + n) * CDIM2 + lane * 8 - 64;
    float pos = 0.f, neg = 0.f;
#pragma unroll
    for (int t = 0; t < 2; t++) {
        float4 a = ((const float4*)au)[t];
        float4 b = ((const float4*)bp)[t];
        float4 c = ((const float4*)bn)[t];
        pos += a.x * b.x + a.y * b.y + a.z * b.z + a.w * b.w;
        neg += a.x * c.x + a.y * c.y + a.z * c.z + a.w * c.w;
    }
    float2 a0 = ((const float2*)(ue0 + (size_t)u * DIM))[lane];
    float2 b0 = ((const float2*)(ie0 + (size_t)p * DIM))[lane];
    float2 c0 = ((const float2*)(ie0 + (size_t)n * DIM))[lane];
    float rg = a0.x * a0.x + a0.y * a0.y + b0.x * b0.x + b0.y * b0.y + c0.x * c0.x + c0.y * c0.y;
#pragma unroll
    for (int o = 16; o; o >>= 1) {
        pos += __shfl_xor_sync(0xFFFFFFFFu, pos, o);
        neg += __shfl_xor_sync(0xFFFFFFFFu, neg, o);
        rg  += __shfl_xor_sync(0xFFFFFFFFu, rg,  o);
    }
    if (lane == 0) {
        float x = pos - neg;
        float ls = fminf(x, 0.f) - log1pf(expf(-fabsf(x)));  // stable log_sigmoid
        atomicAdd(&g_acc[0], ls);
        atomicAdd(&g_acc[1], rg);
    }
}

__global__ void fin_kernel(float* out, int osz) {
    float bpr = -g_acc[0] / (float)BSZ;
    float reg = 1e-4f * 0.5f * g_acc[1] / (float)BSZ;
    if (osz >= 3) { out[0] = bpr + reg; out[1] = bpr; out[2] = reg; }
    else          { out[0] = bpr + reg; }
}

// ---------------- launch ----------------
extern "C" void kernel_launch(void* const* d_in, const int* in_sizes, int n_in,
                              void* d_out, int out_size) {
    const float* user_emb = (const float*)d_in[0];
    const float* item_emb = (const float*)d_in[1];
    const float* W_gc     = (const float*)d_in[2];
    const float* b_gc     = (const float*)d_in[3];
    const float* W_bi     = (const float*)d_in[4];
    const float* b_bi     = (const float*)d_in[5];
    const float* val      = (const float*)d_in[6];
    const int*   row      = (const int*)d_in[7];
    const int*   col      = (const int*)d_in[8];
    const int*   uid      = (const int*)d_in[9];
    const int*   pid      = (const int*)d_in[10];
    const int*   nid      = (const int*)d_in[11];

    // derived threefry keys: base key = (0, 42); fold_in(d) = threefry(key, (0, d))
    uint32_t ke0, ke1;
    threefry2x32(0u, 42u, 0u, 0u, ke0, ke1);

    const size_t SMEM = (8192 + 4 * 64 * 65 * 2 + 256 * 4) * sizeof(float); // ~170 KB
    cudaFuncSetAttribute(combine_kernel, cudaFuncAttributeMaxDynamicSharedMemorySize, (int)SMEM);
    void* cnt_ptr = nullptr;
    cudaGetSymbolAddress(&cnt_ptr, g_cnt);
    float* g_ego_ptr = nullptr;
    { void* tmp = nullptr; cudaGetSymbolAddress(&tmp, g_ego); g_ego_ptr = (float*)tmp; }

    cudaMemsetAsync(cnt_ptr, 0, NTOT * sizeof(int));
    scatter_kernel<<<(NNZE + 255) / 256, 256>>>(val, row, col, ke0, ke1);

    for (int k = 0; k < NLAY; k++) {
        const float* eu = (k == 0) ? user_emb : g_ego_ptr;
        const float* ei = (k == 0) ? item_emb : g_ego_ptr + (size_t)UNUM * DIM;
        spmm_kernel<<<(NTOT * 32 + 255) / 256, 256>>>(eu, ei);
        uint32_t km0, km1;
        threefry2x32(0u, 42u, 0u, (uint32_t)(k + 1), km0, km1);
        combine_kernel<<<(NTOT + RPB - 1) / RPB, 256, SMEM>>>(
            W_gc + k * 4096, b_gc + k * 64, W_bi + k * 4096, b_bi + k * 64,
            eu, ei, km0, km1, k, (k != NLAY - 1) ? 1 : 0);
    }

    loss_kernel<<<(BSZ * 32 + 255) / 256, 256>>>(user_emb, item_emb, uid, pid, nid);
    fin_kernel<<<1, 1>>>((float*)d_out, out_size);
}

// round 6
// speedup vs baseline: 1.0326x; 1.0326x over previous
#include <cuda_runtime.h>
#include <cstdint>

#define UNUM 100000
#define INUM 200000
#define NTOT 300000
#define NNZE 4000000
#define BSZ  4096
#define DIM  64
#define NLAY 3
#define CDIM2 192             // concat store: layers 1..3 only (layer0 read from inputs)
#define EMAX 96               // padded ELL row capacity (mean deg ~12)
#define RPB  128              // rows per combine block

// ---------------- scratch (static device globals; no allocs allowed) ----------------
__device__ __align__(256) float g_ego [(size_t)NTOT * DIM];          // 76.8 MB
__device__ __align__(256) float g_side[(size_t)NTOT * DIM];          // 76.8 MB
__device__ __align__(256) float g_all [(size_t)NTOT * CDIM2];        // 230 MB
__device__ __align__(256) int2  g_ell [(size_t)NTOT * EMAX];         // 230 MB {col, val bits}
__device__ __align__(256) int   g_cnt [NTOT];
__device__ float g_acc[2];                                           // bpr_sum, reg_sum

// ---------------- threefry2x32 (exact JAX semantics) ----------------
__host__ __device__ __forceinline__ uint32_t rotl32(uint32_t x, int r) {
    return (x << r) | (x >> (32 - r));
}

__host__ __device__ inline void threefry2x32(uint32_t k0, uint32_t k1,
                                             uint32_t x0, uint32_t x1,
                                             uint32_t &o0, uint32_t &o1) {
    uint32_t k2 = k0 ^ k1 ^ 0x1BD11BDAu;
    x0 += k0; x1 += k1;
#define TF_R(r) { x0 += x1; x1 = rotl32(x1, r); x1 ^= x0; }
    TF_R(13) TF_R(15) TF_R(26) TF_R(6)   x0 += k1; x1 += k2 + 1u;
    TF_R(17) TF_R(29) TF_R(16) TF_R(24)  x0 += k2; x1 += k0 + 2u;
    TF_R(13) TF_R(15) TF_R(26) TF_R(6)   x0 += k0; x1 += k1 + 3u;
    TF_R(17) TF_R(29) TF_R(16) TF_R(24)  x0 += k1; x1 += k2 + 4u;
    TF_R(13) TF_R(15) TF_R(26) TF_R(6)   x0 += k2; x1 += k0 + 5u;
#undef TF_R
    o0 = x0; o1 = x1;
}

// Partitionable (counter-mode) bits: threefry(key, (0, i)), 32-bit finisher o0^o1
__device__ __forceinline__ uint32_t rbits_partitionable(uint32_t k0, uint32_t k1, uint32_t i) {
    uint32_t o0, o1;
    threefry2x32(k0, k1, 0u, i, o0, o1);
    return o0 ^ o1;
}

__device__ __forceinline__ float u01(uint32_t bits) {
    return __uint_as_float((bits >> 9) | 0x3F800000u) - 1.0f;
}

// layer-aware ego row pointer (layer 0 reads raw inputs; layers >0 read g_ego)
__device__ __forceinline__ const float* ego_row(const float* eu, const float* ei, int r) {
    return (r < UNUM) ? eu + (size_t)r * DIM : ei + (size_t)(r - UNUM) * DIM;
}

// ---------------- kernels ----------------
// One pass: edge dropout + ELL scatter (dropped edges never stored). Also zeroes acc.
__global__ void scatter_kernel(const float* __restrict__ val, const int* __restrict__ row,
                               const int* __restrict__ col, uint32_t k0, uint32_t k1) {
    int e = blockIdx.x * blockDim.x + threadIdx.x;
    if (e == 0) { g_acc[0] = 0.f; g_acc[1] = 0.f; }
    if (e >= NNZE) return;
    float u = u01(rbits_partitionable(k0, k1, (uint32_t)e));
    if (u >= 0.9f) return;                 // dropped: contributes +0 exactly
    float v = val[e] * (1.0f / 0.9f);
    int r = row[e];
    int pos = atomicAdd(&g_cnt[r], 1);
    if (pos < EMAX)
        g_ell[(size_t)r * EMAX + pos] = make_int2(col[e], __float_as_int(v));
}

// Atomic-free SpMM: one warp per row; 2 edge-slots x 16 dim-lanes,
// 4-way unroll inside each slot for MLP.
__global__ void spmm_kernel(const float* __restrict__ eu, const float* __restrict__ ei) {
    int w    = (blockIdx.x * blockDim.x + threadIdx.x) >> 5;
    if (w >= NTOT) return;
    int lane = threadIdx.x & 31;
    int sub  = lane >> 4;       // which edge slot
    int dl   = lane & 15;       // dim quarter (float4)
    int cnt  = g_cnt[w];
    if (cnt > EMAX) cnt = EMAX;
    const int2* ep = g_ell + (size_t)w * EMAX;
    float4 acc = make_float4(0.f, 0.f, 0.f, 0.f);
    int j = sub;
    // 4 independent edges in flight per thread
    for (; j + 6 < cnt; j += 8) {
        int2 cva = ep[j];
        int2 cvb = ep[j + 2];
        int2 cvc = ep[j + 4];
        int2 cvd = ep[j + 6];
        float4 xa = ((const float4*)ego_row(eu, ei, cva.x))[dl];
        float4 xb = ((const float4*)ego_row(eu, ei, cvb.x))[dl];
        float4 xc = ((const float4*)ego_row(eu, ei, cvc.x))[dl];
        float4 xd = ((const float4*)ego_row(eu, ei, cvd.x))[dl];
        float va = __int_as_float(cva.y), vb = __int_as_float(cvb.y);
        float vc = __int_as_float(cvc.y), vd = __int_as_float(cvd.y);
        acc.x += va * xa.x + vb * xb.x + vc * xc.x + vd * xd.x;
        acc.y += va * xa.y + vb * xb.y + vc * xc.y + vd * xd.y;
        acc.z += va * xa.z + vb * xb.z + vc * xc.z + vd * xd.z;
        acc.w += va * xa.w + vb * xb.w + vc * xc.w + vd * xd.w;
    }
    for (; j < cnt; j += 2) {
        int2 cv = ep[j];
        float v = __int_as_float(cv.y);
        float4 x = ((const float4*)ego_row(eu, ei, cv.x))[dl];
        acc.x += v * x.x; acc.y += v * x.y; acc.z += v * x.z; acc.w += v * x.w;
    }
    acc.x += __shfl_xor_sync(0xFFFFFFFFu, acc.x, 16);
    acc.y += __shfl_xor_sync(0xFFFFFFFFu, acc.y, 16);
    acc.z += __shfl_xor_sync(0xFFFFFFFFu, acc.z, 16);
    acc.w += __shfl_xor_sync(0xFFFFFFFFu, acc.w, 16);
    if (sub == 0)
        ((float4*)(g_side + (size_t)w * DIM))[dl] = acc;
}

// Fused: side@Wg + b + (ego*side)@Wb + b -> leaky_relu -> msg dropout -> L2 norm.
// 256 threads, 128 rows/block, 2 rows x 16 cols per thread, ~102 KB smem -> 2 CTAs/SM.
__global__ void __launch_bounds__(256, 2)
combine_kernel(const float* __restrict__ Wg, const float* __restrict__ bg,
               const float* __restrict__ Wb, const float* __restrict__ bb,
               const float* __restrict__ eu, const float* __restrict__ ei,
               uint32_t mk0, uint32_t mk1, int layer, int write_ego) {
    extern __shared__ float sm[];
    float*  sWg = sm;                       // 4096
    float*  sWb = sm + 4096;                // 4096
    float2* sSE = (float2*)(sm + 8192);     // 2 planes x 64 x 65 float2 {s, e*s}
    const int PL2 = 64 * 65;
    float*  ssum = sm + 8192 + 2 * PL2 * 2; // 128 x 4
    int tid  = threadIdx.x;
    int row0 = blockIdx.x * RPB;

    for (int i = tid; i < 4096; i += 256) { sWg[i] = Wg[i]; sWb[i] = Wb[i]; }
    for (int i = tid; i < RPB * 16; i += 256) {
        int r = i >> 4, q = i & 15;
        int gr = row0 + r;
        float4 s = make_float4(0.f, 0.f, 0.f, 0.f), e = s;
        if (gr < NTOT) {
            s = ((const float4*)(g_side + (size_t)gr * DIM))[q];
            e = ((const float4*)ego_row(eu, ei, gr))[q];
        }
        int p = r & 1, rp = r >> 1;
        float2* d = &sSE[p * PL2 + rp * 65 + q * 4];
        d[0] = make_float2(s.x, s.x * e.x);
        d[1] = make_float2(s.y, s.y * e.y);
        d[2] = make_float2(s.z, s.z * e.z);
        d[3] = make_float2(s.w, s.w * e.w);
    }
    __syncthreads();

    int cg = tid >> 6;           // 0..3 column group (warp-uniform)
    int rp = tid & 63;           // row pair index
    int c0 = cg * 16;
    float acc[2][16];
#pragma unroll
    for (int c = 0; c < 16; c++) {
        float b = bg[c0 + c] + bb[c0 + c];
        acc[0][c] = b; acc[1][c] = b;
    }

    for (int j = 0; j < 64; j++) {
        float2 se0 = sSE[0 * PL2 + rp * 65 + j];
        float2 se1 = sSE[1 * PL2 + rp * 65 + j];
        const float4* wg4 = (const float4*)&sWg[j * 64 + c0];
        const float4* wb4 = (const float4*)&sWb[j * 64 + c0];
#pragma unroll
        for (int q = 0; q < 4; q++) {
            float4 wg = wg4[q], wb = wb4[q];
            acc[0][4*q+0] += se0.x * wg.x + se0.y * wb.x;
            acc[0][4*q+1] += se0.x * wg.y + se0.y * wb.y;
            acc[0][4*q+2] += se0.x * wg.z + se0.y * wb.z;
            acc[0][4*q+3] += se0.x * wg.w + se0.y * wb.w;
            acc[1][4*q+0] += se1.x * wg.x + se1.y * wb.x;
            acc[1][4*q+1] += se1.x * wg.y + se1.y * wb.y;
            acc[1][4*q+2] += se1.x * wg.z + se1.y * wb.z;
            acc[1][4*q+3] += se1.x * wg.w + se1.y * wb.w;
        }
    }

    // epilogue: leaky-relu + message dropout + partial row sums
#pragma unroll
    for (int p = 0; p < 2; p++) {
        int gr = row0 + rp * 2 + p;
        float ss = 0.f;
        if (gr < NTOT) {
            uint32_t ib = (uint32_t)gr * 64u + (uint32_t)c0;
#pragma unroll
            for (int c = 0; c < 16; c++) {
                float a = acc[p][c];
                a = (a >= 0.f) ? a : 0.2f * a;
                float u = u01(rbits_partitionable(mk0, mk1, ib + (uint32_t)c));
                a = (u < 0.9f) ? a * (1.0f / 0.9f) : 0.f;
                acc[p][c] = a;
                ss += a * a;
            }
        }
        ssum[(rp * 2 + p) * 4 + cg] = ss;
    }
    __syncthreads();

#pragma unroll
    for (int p = 0; p < 2; p++) {
        int gr = row0 + rp * 2 + p;
        if (gr >= NTOT) continue;
        int rb = rp * 2 + p;
        float tot = ssum[rb * 4 + 0] + ssum[rb * 4 + 1] + ssum[rb * 4 + 2] + ssum[rb * 4 + 3];
        float inv = 1.0f / fmaxf(sqrtf(tot), 1e-12f);
        float4* dn = (float4*)(g_all + (size_t)gr * CDIM2 + (size_t)layer * DIM + c0);
#pragma unroll
        for (int q = 0; q < 4; q++)
            dn[q] = make_float4(acc[p][4*q+0] * inv, acc[p][4*q+1] * inv,
                                acc[p][4*q+2] * inv, acc[p][4*q+3] * inv);
        if (write_ego) {
            float4* de = (float4*)(g_ego + (size_t)gr * DIM + c0);
#pragma unroll
            for (int q = 0; q < 4; q++)
                de[q] = make_float4(acc[p][4*q+0], acc[p][4*q+1],
                                    acc[p][4*q+2], acc[p][4*q+3]);
        }
    }
}

// warp per sample: BPR + reg partial sums. Concat = [raw emb | g_all(192)].
__global__ void loss_kernel(const float* __restrict__ ue0, const float* __restrict__ ie0,
                            const int* __restrict__ uid, const int* __restrict__ pid,
                            const int* __restrict__ nid) {
    int w    = (blockIdx.x * blockDim.x + threadIdx.x) >> 5;
    int lane = threadIdx.x & 31;
    if (w >= BSZ) return;
    int u = uid[w], p = pid[w], n = nid[w];
    const float* au = (lane < 8) ? ue0 + (size_t)u * DIM + lane * 8
                                 : g_all + (size_t)u * CDIM2 + lane * 8 - 64;
    const float* bp = (lane < 8) ? ie0 + (size_t)p * DIM + lane * 8
                                 : g_all + (size_t)(UNUM + p) * CDIM2 + lane * 8 - 64;
    const float* bn = (lane < 8) ? ie0 + (size_t)n * DIM + lane * 8
                                 : g_all + (size_t)(UNUM + n) * CDIM2 + lane * 8 - 64;
    float pos = 0.f, neg = 0.f;
#pragma unroll
    for (int t = 0; t < 2; t++) {
        float4 a = ((const float4*)au)[t];
        float4 b = ((const float4*)bp)[t];
        float4 c = ((const float4*)bn)[t];
        pos += a.x * b.x + a.y * b.y + a.z * b.z + a.w * b.w;
        neg += a.x * c.x + a.y * c.y + a.z * c.z + a.w * c.w;
    }
    float2 a0 = ((const float2*)(ue0 + (size_t)u * DIM))[lane];
    float2 b0 = ((const float2*)(ie0 + (size_t)p * DIM))[lane];
    float2 c0 = ((const float2*)(ie0 + (size_t)n * DIM))[lane];
    float rg = a0.x * a0.x + a0.y * a0.y + b0.x * b0.x + b0.y * b0.y + c0.x * c0.x + c0.y * c0.y;
#pragma unroll
    for (int o = 16; o; o >>= 1) {
        pos += __shfl_xor_sync(0xFFFFFFFFu, pos, o);
        neg += __shfl_xor_sync(0xFFFFFFFFu, neg, o);
        rg  += __shfl_xor_sync(0xFFFFFFFFu, rg,  o);
    }
    if (lane == 0) {
        float x = pos - neg;
        float ls = fminf(x, 0.f) - log1pf(expf(-fabsf(x)));  // stable log_sigmoid
        atomicAdd(&g_acc[0], ls);
        atomicAdd(&g_acc[1], rg);
    }
}

__global__ void fin_kernel(float* out, int osz) {
    float bpr = -g_acc[0] / (float)BSZ;
    float reg = 1e-4f * 0.5f * g_acc[1] / (float)BSZ;
    if (osz >= 3) { out[0] = bpr + reg; out[1] = bpr; out[2] = reg; }
    else          { out[0] = bpr + reg; }
}

// ---------------- launch ----------------
extern "C" void kernel_launch(void* const* d_in, const int* in_sizes, int n_in,
                              void* d_out, int out_size) {
    const float* user_emb = (const float*)d_in[0];
    const float* item_emb = (const float*)d_in[1];
    const float* W_gc     = (const float*)d_in[2];
    const float* b_gc     = (const float*)d_in[3];
    const float* W_bi     = (const float*)d_in[4];
    const float* b_bi     = (const float*)d_in[5];
    const float* val      = (const float*)d_in[6];
    const int*   row      = (const int*)d_in[7];
    const int*   col      = (const int*)d_in[8];
    const int*   uid      = (const int*)d_in[9];
    const int*   pid      = (const int*)d_in[10];
    const int*   nid      = (const int*)d_in[11];

    // derived threefry keys: base key = (0, 42); fold_in(d) = threefry(key, (0, d))
    uint32_t ke0, ke1;
    threefry2x32(0u, 42u, 0u, 0u, ke0, ke1);

    const size_t SMEM = (8192 + 2 * 64 * 65 * 2 + 128 * 4) * sizeof(float); // ~102 KB
    cudaFuncSetAttribute(combine_kernel, cudaFuncAttributeMaxDynamicSharedMemorySize, (int)SMEM);
    void* cnt_ptr = nullptr;
    cudaGetSymbolAddress(&cnt_ptr, g_cnt);
    float* g_ego_ptr = nullptr;
    { void* tmp = nullptr; cudaGetSymbolAddress(&tmp, g_ego); g_ego_ptr = (float*)tmp; }

    cudaMemsetAsync(cnt_ptr, 0, NTOT * sizeof(int));
    scatter_kernel<<<(NNZE + 255) / 256, 256>>>(val, row, col, ke0, ke1);

    for (int k = 0; k < NLAY; k++) {
        const float* eu = (k == 0) ? user_emb : g_ego_ptr;
        const float* ei = (k == 0) ? item_emb : g_ego_ptr + (size_t)UNUM * DIM;
        spmm_kernel<<<(NTOT * 32 + 255) / 256, 256>>>(eu, ei);
        uint32_t km0, km1;
        threefry2x32(0u, 42u, 0u, (uint32_t)(k + 1), km0, km1);
        combine_kernel<<<(NTOT + RPB - 1) / RPB, 256, SMEM>>>(
            W_gc + k * 4096, b_gc + k * 64, W_bi + k * 4096, b_bi + k * 64,
            eu, ei, km0, km1, k, (k != NLAY - 1) ? 1 : 0);
    }

    loss_kernel<<<(BSZ * 32 + 255) / 256, 256>>>(user_emb, item_emb, uid, pid, nid);
    fin_kernel<<<1, 1>>>((float*)d_out, out_size);
}